// round 10
// baseline (speedup 1.0000x reference)
#include <cuda_runtime.h>
#include <cuda_bf16.h>
#include <math.h>

#define NN 100000
#define NE 1200000
#define D 64
#define NG 512
#define NL 3
#define BN_EPS 1e-5

#define SCAN_BLK 1024
#define NSCAN ((NN + SCAN_BLK - 1) / SCAN_BLK)   // 98

// Scratch (static device arrays; allocation is forbidden)
__device__ float g_agg[(size_t)NN * D];   // holds agg + x (fused)
__device__ float g_h[(size_t)NN * D];
__device__ float g_x[(size_t)NN * D];
__device__ double g_stats[2 * D];
__device__ float g_mu[D];
__device__ float g_rs[D];
__device__ int g_deg[NN];
__device__ int g_rowptr[NN];
__device__ int g_cursor[NN];
__device__ int g_bsum[NSCAN];
__device__ int2 g_edge[NE];               // {src, __float_as_int(w)}

// ---------------------------------------------------------------------------
// tf32 helpers
// ---------------------------------------------------------------------------
__device__ __forceinline__ unsigned f2tf(float x) {
    unsigned r;
    asm("cvt.rna.tf32.f32 %0, %1;" : "=r"(r) : "f"(x));
    return r;
}
__device__ __forceinline__ void mma_tf32(float* c, unsigned a0, unsigned a1,
                                         unsigned a2, unsigned a3,
                                         unsigned b0, unsigned b1) {
    asm volatile(
        "mma.sync.aligned.m16n8k8.row.col.f32.tf32.tf32.f32 "
        "{%0,%1,%2,%3}, {%4,%5,%6,%7}, {%8,%9}, {%0,%1,%2,%3};\n"
        : "+f"(c[0]), "+f"(c[1]), "+f"(c[2]), "+f"(c[3])
        : "r"(a0), "r"(a1), "r"(a2), "r"(a3), "r"(b0), "r"(b1));
}

// ---------------------------------------------------------------------------
// init: zero deg, stats, pooled-output region
// ---------------------------------------------------------------------------
__global__ void init_kernel(float* __restrict__ out_pool) {
    int gid = blockIdx.x * blockDim.x + threadIdx.x;
    int stride = gridDim.x * blockDim.x;
    for (int i = gid; i < NN; i += stride) g_deg[i] = 0;
    if (out_pool)
        for (int i = gid; i < NG * (NL * D); i += stride) out_pool[i] = 0.f;
    if (gid < 2 * D) g_stats[gid] = 0.0;
}

// ---------------------------------------------------------------------------
// CSR build: histogram, scan, fill
// ---------------------------------------------------------------------------
__global__ void deg_kernel(const int* __restrict__ ei) {
    int e = blockIdx.x * blockDim.x + threadIdx.x;
    if (e < NE) {
        int dst = ei[NE + e];
        if ((unsigned)dst < NN) atomicAdd(&g_deg[dst], 1);
    }
}

__global__ void __launch_bounds__(SCAN_BLK) scanA_kernel() {
    __shared__ int sh[SCAN_BLK];
    int t = threadIdx.x;
    int i = blockIdx.x * SCAN_BLK + t;
    int v = (i < NN) ? g_deg[i] : 0;
    sh[t] = v;
    __syncthreads();
    for (int off = 1; off < SCAN_BLK; off <<= 1) {
        int add = (t >= off) ? sh[t - off] : 0;
        __syncthreads();
        sh[t] += add;
        __syncthreads();
    }
    if (i < NN) g_rowptr[i] = sh[t] - v;          // exclusive within block
    if (t == SCAN_BLK - 1) g_bsum[blockIdx.x] = sh[t];
}

__global__ void scanB_kernel() {                  // parallel scan of 98 blocks
    __shared__ int sh[128];
    int t = threadIdx.x;
    int v = (t < NSCAN) ? g_bsum[t] : 0;
    sh[t] = v;
    __syncthreads();
    for (int off = 1; off < 128; off <<= 1) {
        int add = (t >= off) ? sh[t - off] : 0;
        __syncthreads();
        sh[t] += add;
        __syncthreads();
    }
    if (t < NSCAN) g_bsum[t] = sh[t] - v;         // exclusive
}

__global__ void scanC_kernel() {
    int i = blockIdx.x * blockDim.x + threadIdx.x;
    if (i < NN) {
        int r = g_rowptr[i] + g_bsum[i / SCAN_BLK];
        g_rowptr[i] = r;
        g_cursor[i] = r;
    }
}

__global__ void fill_kernel(const int* __restrict__ ei,
                            const float* __restrict__ ew) {
    int e = blockIdx.x * blockDim.x + threadIdx.x;
    if (e < NE) {
        int src = ei[e];
        int dst = ei[NE + e];
        if ((unsigned)dst >= NN) return;
        int pos = atomicAdd(&g_cursor[dst], 1);
        g_edge[pos] = make_int2(src, __float_as_int(ew[e]));
    }
}

// ---------------------------------------------------------------------------
// gather-aggregate: warp per node. agg[n] = x[n] + sum_e w_e * x[src_e]
// ---------------------------------------------------------------------------
__global__ void __launch_bounds__(256) agg_kernel(const float* __restrict__ x_in,
                                                  int use_gx) {
    const float* __restrict__ x = use_gx ? g_x : x_in;
    int wid = (blockIdx.x * blockDim.x + threadIdx.x) >> 5;
    int lane = threadIdx.x & 31;
    if (wid >= NN) return;
    int start = g_rowptr[wid];
    int deg = g_deg[wid];
    float a0 = 0.f, a1 = 0.f;
    int e = 0;
    for (; e + 2 <= deg; e += 2) {
        int2 e0 = g_edge[start + e];
        int2 e1 = g_edge[start + e + 1];
        float w0 = __int_as_float(e0.y);
        float w1 = __int_as_float(e1.y);
        const float* r0 = x + (size_t)e0.x * D;
        const float* r1 = x + (size_t)e1.x * D;
        a0 += w0 * r0[lane];
        a1 += w0 * r0[lane + 32];
        a0 += w1 * r1[lane];
        a1 += w1 * r1[lane + 32];
    }
    if (e < deg) {
        int2 e0 = g_edge[start + e];
        float w0 = __int_as_float(e0.y);
        const float* r0 = x + (size_t)e0.x * D;
        a0 += w0 * r0[lane];
        a1 += w0 * r0[lane + 32];
    }
    const float* xn = x + (size_t)wid * D;
    g_agg[(size_t)wid * D + lane] = a0 + xn[lane];
    g_agg[(size_t)wid * D + lane + 32] = a1 + xn[lane + 32];
}

// ---------------------------------------------------------------------------
// fused MLP on tensor cores (3xTF32 mma.m16n8k8, fp32 accumulate):
//   h = relu(relu(A@W1^T + b1)@W2^T + b2), + BN partial sums
// A = g_agg (includes +x). 64-row tile, 8 warps; warp tile 16(M) x 32(N).
// shA: A rows [m][k] stride 68. shW: W row-major [n][k] stride 68
// (B operand of mma is col-major K x N, i.e. B[k][n] = W[n][k]).
// ---------------------------------------------------------------------------
__global__ void __launch_bounds__(256) mlp_kernel(
    const float* __restrict__ W1, const float* __restrict__ b1,
    const float* __restrict__ W2, const float* __restrict__ b2) {
    __shared__ __align__(16) float shA[64 * 68];
    __shared__ __align__(16) float shW[64 * 68];
    __shared__ float red[2 * D];

    int tid = threadIdx.x;
    int base = blockIdx.x * 64;
    if (tid < 2 * D) red[tid] = 0.f;

#pragma unroll
    for (int j = 0; j < 16; j++) {
        int idx = tid + j * 256;
        int r = idx >> 6, k = idx & 63;
        int n = base + r;
        shA[r * 68 + k] = (n < NN) ? g_agg[(size_t)n * D + k] : 0.f;
    }
    // shW row-major: shW[n][k] = W1[n*64+k]
#pragma unroll
    for (int j = 0; j < 16; j++) {
        int idx = tid + j * 256;
        shW[(idx >> 6) * 68 + (idx & 63)] = W1[idx];
    }
    __syncthreads();

    int w = tid >> 5;
    int lane = tid & 31;
    int m0 = (w & 3) * 16;        // warp M offset
    int n0 = (w >> 2) * 32;       // warp N offset
    int g = lane >> 2;            // group id 0..7
    int t = lane & 3;             // thread in group

    float c[4][4];

#define DO_GEMM()                                                              \
    do {                                                                       \
        _Pragma("unroll")                                                      \
        for (int f = 0; f < 4; f++)                                            \
            _Pragma("unroll")                                                  \
            for (int r = 0; r < 4; r++) c[f][r] = 0.f;                         \
        _Pragma("unroll")                                                      \
        for (int s = 0; s < 8; s++) {                                          \
            int k0 = s * 8;                                                    \
            float af0 = shA[(m0 + g) * 68 + k0 + t];                           \
            float af1 = shA[(m0 + g + 8) * 68 + k0 + t];                       \
            float af2 = shA[(m0 + g) * 68 + k0 + t + 4];                       \
            float af3 = shA[(m0 + g + 8) * 68 + k0 + t + 4];                   \
            unsigned ah0 = f2tf(af0), ah1 = f2tf(af1);                         \
            unsigned ah2 = f2tf(af2), ah3 = f2tf(af3);                         \
            unsigned al0 = f2tf(af0 - __uint_as_float(ah0));                   \
            unsigned al1 = f2tf(af1 - __uint_as_float(ah1));                   \
            unsigned al2 = f2tf(af2 - __uint_as_float(ah2));                   \
            unsigned al3 = f2tf(af3 - __uint_as_float(ah3));                   \
            _Pragma("unroll")                                                  \
            for (int f = 0; f < 4; f++) {                                      \
                int nb = n0 + f * 8;                                           \
                float bf0 = shW[(nb + g) * 68 + k0 + t];                       \
                float bf1 = shW[(nb + g) * 68 + k0 + t + 4];                   \
                unsigned bh0 = f2tf(bf0), bh1 = f2tf(bf1);                     \
                unsigned bl0 = f2tf(bf0 - __uint_as_float(bh0));               \
                unsigned bl1 = f2tf(bf1 - __uint_as_float(bh1));               \
                mma_tf32(c[f], ah0, ah1, ah2, ah3, bh0, bh1);                  \
                mma_tf32(c[f], al0, al1, al2, al3, bh0, bh1);                  \
                mma_tf32(c[f], ah0, ah1, ah2, ah3, bl0, bl1);                  \
            }                                                                  \
        }                                                                      \
    } while (0)

    // GEMM1
    DO_GEMM();
    __syncthreads();   // all warps done reading shA/shW

    // epilogue1: t1 = relu(z + b1) -> shA (becomes A of GEMM2)
#pragma unroll
    for (int f = 0; f < 4; f++) {
        int cl = n0 + f * 8 + 2 * t;
        float bb0 = b1[cl], bb1 = b1[cl + 1];
        float2 v0 = make_float2(fmaxf(c[f][0] + bb0, 0.f),
                                fmaxf(c[f][1] + bb1, 0.f));
        float2 v1 = make_float2(fmaxf(c[f][2] + bb0, 0.f),
                                fmaxf(c[f][3] + bb1, 0.f));
        *(float2*)&shA[(m0 + g) * 68 + cl] = v0;
        *(float2*)&shA[(m0 + g + 8) * 68 + cl] = v1;
    }
    // reload shW with W2
#pragma unroll
    for (int j = 0; j < 16; j++) {
        int idx = tid + j * 256;
        shW[(idx >> 6) * 68 + (idx & 63)] = W2[idx];
    }
    __syncthreads();

    // GEMM2
    DO_GEMM();

    // epilogue2: h = relu(z + b2), store, BN partial sums
    int node0 = base + m0 + g;
    int node1 = node0 + 8;
    bool ok0 = node0 < NN, ok1 = node1 < NN;
#pragma unroll
    for (int f = 0; f < 4; f++) {
        int cl = n0 + f * 8 + 2 * t;
        float bb0 = b2[cl], bb1 = b2[cl + 1];
        float v00 = fmaxf(c[f][0] + bb0, 0.f);
        float v01 = fmaxf(c[f][1] + bb1, 0.f);
        float v10 = fmaxf(c[f][2] + bb0, 0.f);
        float v11 = fmaxf(c[f][3] + bb1, 0.f);
        float s0 = 0.f, s1 = 0.f, q0 = 0.f, q1 = 0.f;
        if (ok0) {
            *(float2*)&g_h[(size_t)node0 * D + cl] = make_float2(v00, v01);
            s0 += v00; s1 += v01; q0 += v00 * v00; q1 += v01 * v01;
        }
        if (ok1) {
            *(float2*)&g_h[(size_t)node1 * D + cl] = make_float2(v10, v11);
            s0 += v10; s1 += v11; q0 += v10 * v10; q1 += v11 * v11;
        }
        atomicAdd(&red[cl], s0);
        atomicAdd(&red[cl + 1], s1);
        atomicAdd(&red[D + cl], q0);
        atomicAdd(&red[D + cl + 1], q1);
    }
    __syncthreads();
    if (tid < 2 * D) atomicAdd(&g_stats[tid], (double)red[tid]);
#undef DO_GEMM
}

// ---------------------------------------------------------------------------
// finalize BN stats (and reset accumulators for next layer)
// ---------------------------------------------------------------------------
__global__ void finalize_kernel() {
    int f = threadIdx.x;
    double s = g_stats[f];
    double q = g_stats[D + f];
    double mu = s / (double)NN;
    double var = q / (double)NN - mu * mu;
    g_mu[f] = (float)mu;
    g_rs[f] = (float)(1.0 / sqrt(var + (double)BN_EPS));
    g_stats[f] = 0.0;
    g_stats[D + f] = 0.0;
}

// ---------------------------------------------------------------------------
// normalize + write xs + next-layer x + pooled segment-sum (batch sorted)
// ---------------------------------------------------------------------------
__global__ void norm_kernel(const float* __restrict__ gamma,
                            const float* __restrict__ beta,
                            const int* __restrict__ batch,
                            float* __restrict__ out_pool,
                            float* __restrict__ out_xs, int layer) {
    int tid = threadIdx.x;
    int f = tid & 63;
    int sub = tid >> 6;   // 0..3
    int base = blockIdx.x * 128;
    float gm = gamma[f], bt = beta[f], mu = g_mu[f], rs = g_rs[f];
    int gcur = -1;
    float acc = 0.f;
    for (int j = 0; j < 32; j++) {
        int n = base + sub + j * 4;
        if (n >= NN) break;
        float h = g_h[(size_t)n * D + f];
        float y = gm * (h - mu) * rs + bt;
        if (out_xs)
            out_xs[(size_t)n * (NL * D) + layer * D + f] = y;
        g_x[(size_t)n * D + f] = y;
        if (out_pool) {
            int g = batch[n];
            if (g != gcur) {
                if (gcur >= 0 && gcur < NG)
                    atomicAdd(&out_pool[(size_t)gcur * (NL * D) + layer * D + f], acc);
                gcur = g;
                acc = 0.f;
            }
            acc += y;
        }
    }
    if (out_pool && gcur >= 0 && gcur < NG)
        atomicAdd(&out_pool[(size_t)gcur * (NL * D) + layer * D + f], acc);
}

// ---------------------------------------------------------------------------
extern "C" void kernel_launch(void* const* d_in, const int* in_sizes, int n_in,
                              void* d_out, int out_size) {
    const float *x = 0, *ew = 0, *W1 = 0, *b1 = 0, *W2 = 0, *b2 = 0,
                *gamma = 0, *beta = 0;
    const int *ei = 0, *batch = 0;
    int n12288 = 0, n192 = 0;
    for (int i = 0; i < n_in; i++) {
        int s = in_sizes[i];
        const void* p = d_in[i];
        if (s == NN * D) x = (const float*)p;
        else if (s == 2 * NE) ei = (const int*)p;
        else if (s == NE) ew = (const float*)p;
        else if (s == NN) batch = (const int*)p;
        else if (s == NL * D * D) {
            if (n12288 == 0) W1 = (const float*)p; else W2 = (const float*)p;
            n12288++;
        } else if (s == NL * D) {
            if (n192 == 0) b1 = (const float*)p;
            else if (n192 == 1) b2 = (const float*)p;
            else if (n192 == 2) gamma = (const float*)p;
            else beta = (const float*)p;
            n192++;
        }
    }

    float* out = (float*)d_out;
    float* out_pool = 0;
    float* out_xs = 0;
    const int POOL_SZ = NG * NL * D;     // 98304
    const int XS_SZ = NN * NL * D;       // 19200000
    if (out_size >= POOL_SZ + XS_SZ) { out_pool = out; out_xs = out + POOL_SZ; }
    else if (out_size >= XS_SZ) { out_xs = out; }
    else { out_pool = out; }

    init_kernel<<<256, 256>>>(out_pool);

    // CSR build (once per call, amortized over 3 layers)
    deg_kernel<<<(NE + 255) / 256, 256>>>(ei);
    scanA_kernel<<<NSCAN, SCAN_BLK>>>();
    scanB_kernel<<<1, 128>>>();
    scanC_kernel<<<(NN + 255) / 256, 256>>>();
    fill_kernel<<<(NE + 255) / 256, 256>>>(ei, ew);

    int agg_blocks = (NN * 32 + 255) / 256;          // 12500
    int mlp_blocks = (NN + 63) / 64;                 // 1563
    int norm_blocks = (NN + 127) / 128;              // 782

    for (int i = 0; i < NL; i++) {
        int use_gx = (i > 0) ? 1 : 0;
        agg_kernel<<<agg_blocks, 256>>>(x, use_gx);
        mlp_kernel<<<mlp_blocks, 256>>>(W1 + i * D * D, b1 + i * D,
                                        W2 + i * D * D, b2 + i * D);
        finalize_kernel<<<1, D>>>();
        norm_kernel<<<norm_blocks, 256>>>(gamma + i * D, beta + i * D,
                                          batch, out_pool, out_xs, i);
    }
}

// round 11
// speedup vs baseline: 1.0537x; 1.0537x over previous
#include <cuda_runtime.h>
#include <cuda_fp16.h>
#include <math.h>

#define NN 100000
#define NE 1200000
#define D 64
#define NG 512
#define NL 3
#define BN_EPS 1e-5

#define SCAN_BLK 1024
#define NSCAN ((NN + SCAN_BLK - 1) / SCAN_BLK)   // 98

// Scratch (static device arrays; allocation is forbidden)
__device__ float g_agg[(size_t)NN * D];   // holds agg + x (fused)
__device__ float g_h[(size_t)NN * D];
__device__ float g_x[(size_t)NN * D];
__device__ double g_stats[2 * D];
__device__ float g_mu[D];
__device__ float g_rs[D];
__device__ int g_deg[NN];
__device__ int g_rowptr[NN];
__device__ int g_cursor[NN];
__device__ int g_bsum[NSCAN];
__device__ int2 g_edge[NE];               // {src, __float_as_int(w)}

// ---------------------------------------------------------------------------
// fp16 helpers: 2-term split, m16n8k16 mma
// ---------------------------------------------------------------------------
__device__ __forceinline__ void split_h(float x, __half* hi, __half* lo) {
    __half h = __float2half_rn(x);
    *hi = h;
    *lo = __float2half_rn(x - __half2float(h));
}
__device__ __forceinline__ void mma_f16(float* c, unsigned a0, unsigned a1,
                                        unsigned a2, unsigned a3,
                                        unsigned b0, unsigned b1) {
    asm volatile(
        "mma.sync.aligned.m16n8k16.row.col.f32.f16.f16.f32 "
        "{%0,%1,%2,%3}, {%4,%5,%6,%7}, {%8,%9}, {%0,%1,%2,%3};\n"
        : "+f"(c[0]), "+f"(c[1]), "+f"(c[2]), "+f"(c[3])
        : "r"(a0), "r"(a1), "r"(a2), "r"(a3), "r"(b0), "r"(b1));
}

// ---------------------------------------------------------------------------
// init: zero deg, stats, pooled-output region
// ---------------------------------------------------------------------------
__global__ void init_kernel(float* __restrict__ out_pool) {
    int gid = blockIdx.x * blockDim.x + threadIdx.x;
    int stride = gridDim.x * blockDim.x;
    for (int i = gid; i < NN; i += stride) g_deg[i] = 0;
    if (out_pool)
        for (int i = gid; i < NG * (NL * D); i += stride) out_pool[i] = 0.f;
    if (gid < 2 * D) g_stats[gid] = 0.0;
}

// ---------------------------------------------------------------------------
// CSR build: histogram, scan, fill
// ---------------------------------------------------------------------------
__global__ void deg_kernel(const int* __restrict__ ei) {
    int e = blockIdx.x * blockDim.x + threadIdx.x;
    if (e < NE) {
        int dst = ei[NE + e];
        if ((unsigned)dst < NN) atomicAdd(&g_deg[dst], 1);
    }
}

__global__ void __launch_bounds__(SCAN_BLK) scanA_kernel() {
    __shared__ int sh[SCAN_BLK];
    int t = threadIdx.x;
    int i = blockIdx.x * SCAN_BLK + t;
    int v = (i < NN) ? g_deg[i] : 0;
    sh[t] = v;
    __syncthreads();
    for (int off = 1; off < SCAN_BLK; off <<= 1) {
        int add = (t >= off) ? sh[t - off] : 0;
        __syncthreads();
        sh[t] += add;
        __syncthreads();
    }
    if (i < NN) g_rowptr[i] = sh[t] - v;          // exclusive within block
    if (t == SCAN_BLK - 1) g_bsum[blockIdx.x] = sh[t];
}

__global__ void scanB_kernel() {                  // parallel scan of 98 blocks
    __shared__ int sh[128];
    int t = threadIdx.x;
    int v = (t < NSCAN) ? g_bsum[t] : 0;
    sh[t] = v;
    __syncthreads();
    for (int off = 1; off < 128; off <<= 1) {
        int add = (t >= off) ? sh[t - off] : 0;
        __syncthreads();
        sh[t] += add;
        __syncthreads();
    }
    if (t < NSCAN) g_bsum[t] = sh[t] - v;         // exclusive
}

__global__ void scanC_kernel() {
    int i = blockIdx.x * blockDim.x + threadIdx.x;
    if (i < NN) {
        int r = g_rowptr[i] + g_bsum[i / SCAN_BLK];
        g_rowptr[i] = r;
        g_cursor[i] = r;
    }
}

__global__ void fill_kernel(const int* __restrict__ ei,
                            const float* __restrict__ ew) {
    int e = blockIdx.x * blockDim.x + threadIdx.x;
    if (e < NE) {
        int src = ei[e];
        int dst = ei[NE + e];
        if ((unsigned)dst >= NN) return;
        int pos = atomicAdd(&g_cursor[dst], 1);
        g_edge[pos] = make_int2(src, __float_as_int(ew[e]));
    }
}

// ---------------------------------------------------------------------------
// gather-aggregate: warp per node. agg[n] = x[n] + sum_e w_e * x[src_e]
// ---------------------------------------------------------------------------
__global__ void __launch_bounds__(256) agg_kernel(const float* __restrict__ x_in,
                                                  int use_gx) {
    const float* __restrict__ x = use_gx ? g_x : x_in;
    int wid = (blockIdx.x * blockDim.x + threadIdx.x) >> 5;
    int lane = threadIdx.x & 31;
    if (wid >= NN) return;
    int start = g_rowptr[wid];
    int deg = g_deg[wid];
    float a0 = 0.f, a1 = 0.f;
    int e = 0;
    for (; e + 2 <= deg; e += 2) {
        int2 e0 = g_edge[start + e];
        int2 e1 = g_edge[start + e + 1];
        float w0 = __int_as_float(e0.y);
        float w1 = __int_as_float(e1.y);
        const float* r0 = x + (size_t)e0.x * D;
        const float* r1 = x + (size_t)e1.x * D;
        a0 += w0 * r0[lane];
        a1 += w0 * r0[lane + 32];
        a0 += w1 * r1[lane];
        a1 += w1 * r1[lane + 32];
    }
    if (e < deg) {
        int2 e0 = g_edge[start + e];
        float w0 = __int_as_float(e0.y);
        const float* r0 = x + (size_t)e0.x * D;
        a0 += w0 * r0[lane];
        a1 += w0 * r0[lane + 32];
    }
    const float* xn = x + (size_t)wid * D;
    g_agg[(size_t)wid * D + lane] = a0 + xn[lane];
    g_agg[(size_t)wid * D + lane + 32] = a1 + xn[lane + 32];
}

// ---------------------------------------------------------------------------
// fused MLP on tensor cores, fp16 2-term split (ah*bh + ah*bl + al*bh),
// fp32 accumulate -> ~fp32 accuracy.  mma.m16n8k16.
// 64-row tile, 8 warps; warp tile 16(M) x 32(N).
// Splits precomputed into smem; mainloop is pure LDS + HMMA.
// Layout: half arrays stride 72 (=36 banks) -> conflict-free frags.
// shA*: A rows [m][k]; shB*: [n][k] (mma B is col-major KxN = W[n][k]).
// ---------------------------------------------------------------------------
__global__ void __launch_bounds__(256) mlp_kernel(
    const float* __restrict__ W1, const float* __restrict__ b1,
    const float* __restrict__ W2, const float* __restrict__ b2) {
    __shared__ __half shAh[64 * 72];
    __shared__ __half shAl[64 * 72];
    __shared__ __half shBh[64 * 72];
    __shared__ __half shBl[64 * 72];
    __shared__ float red[2 * D];

    int tid = threadIdx.x;
    int base = blockIdx.x * 64;
    if (tid < 2 * D) red[tid] = 0.f;

    // load + split A (= g_agg) and W1
#pragma unroll
    for (int j = 0; j < 16; j++) {
        int idx = tid + j * 256;
        int r = idx >> 6, k = idx & 63;
        int n = base + r;
        float a = (n < NN) ? g_agg[(size_t)n * D + k] : 0.f;
        split_h(a, &shAh[r * 72 + k], &shAl[r * 72 + k]);
        split_h(W1[idx], &shBh[r * 72 + k], &shBl[r * 72 + k]);
    }
    __syncthreads();

    int w = tid >> 5;
    int lane = tid & 31;
    int m0 = (w & 3) * 16;        // warp M offset
    int n0 = (w >> 2) * 32;       // warp N offset
    int g = lane >> 2;            // group id 0..7
    int t = lane & 3;             // thread in group

    float c[4][4];

#define LDH(arr, off) (*(const unsigned*)&(arr)[off])

#define DO_GEMM()                                                              \
    do {                                                                       \
        _Pragma("unroll")                                                      \
        for (int f = 0; f < 4; f++)                                            \
            _Pragma("unroll")                                                  \
            for (int r = 0; r < 4; r++) c[f][r] = 0.f;                         \
        _Pragma("unroll")                                                      \
        for (int s = 0; s < 4; s++) {                                          \
            int k0 = s * 16;                                                   \
            int ra = (m0 + g) * 72 + k0 + 2 * t;                               \
            int rb = (m0 + g + 8) * 72 + k0 + 2 * t;                           \
            unsigned ah0 = LDH(shAh, ra), ah1 = LDH(shAh, rb);                 \
            unsigned ah2 = LDH(shAh, ra + 8), ah3 = LDH(shAh, rb + 8);         \
            unsigned al0 = LDH(shAl, ra), al1 = LDH(shAl, rb);                 \
            unsigned al2 = LDH(shAl, ra + 8), al3 = LDH(shAl, rb + 8);         \
            _Pragma("unroll")                                                  \
            for (int f = 0; f < 4; f++) {                                      \
                int nb = (n0 + f * 8 + g) * 72 + k0 + 2 * t;                   \
                unsigned bh0 = LDH(shBh, nb), bh1 = LDH(shBh, nb + 8);         \
                unsigned bl0 = LDH(shBl, nb), bl1 = LDH(shBl, nb + 8);         \
                mma_f16(c[f], ah0, ah1, ah2, ah3, bh0, bh1);                   \
                mma_f16(c[f], ah0, ah1, ah2, ah3, bl0, bl1);                   \
                mma_f16(c[f], al0, al1, al2, al3, bh0, bh1);                   \
            }                                                                  \
        }                                                                      \
    } while (0)

    // GEMM1
    DO_GEMM();
    __syncthreads();   // all warps done reading GEMM1 operands

    // epilogue1: t1 = relu(z + b1) -> split into shA (A of GEMM2)
#pragma unroll
    for (int f = 0; f < 4; f++) {
        int cl = n0 + f * 8 + 2 * t;
        float bb0 = b1[cl], bb1 = b1[cl + 1];
        float v00 = fmaxf(c[f][0] + bb0, 0.f);
        float v01 = fmaxf(c[f][1] + bb1, 0.f);
        float v10 = fmaxf(c[f][2] + bb0, 0.f);
        float v11 = fmaxf(c[f][3] + bb1, 0.f);
        int r0 = (m0 + g) * 72 + cl;
        int r1 = (m0 + g + 8) * 72 + cl;
        split_h(v00, &shAh[r0], &shAl[r0]);
        split_h(v01, &shAh[r0 + 1], &shAl[r0 + 1]);
        split_h(v10, &shAh[r1], &shAl[r1]);
        split_h(v11, &shAh[r1 + 1], &shAl[r1 + 1]);
    }
    // reload + split W2
#pragma unroll
    for (int j = 0; j < 16; j++) {
        int idx = tid + j * 256;
        int r = idx >> 6, k = idx & 63;
        split_h(W2[idx], &shBh[r * 72 + k], &shBl[r * 72 + k]);
    }
    __syncthreads();

    // GEMM2
    DO_GEMM();

    // epilogue2: h = relu(z + b2), store, BN partial sums
    int node0 = base + m0 + g;
    int node1 = node0 + 8;
    bool ok0 = node0 < NN, ok1 = node1 < NN;
#pragma unroll
    for (int f = 0; f < 4; f++) {
        int cl = n0 + f * 8 + 2 * t;
        float bb0 = b2[cl], bb1 = b2[cl + 1];
        float v00 = fmaxf(c[f][0] + bb0, 0.f);
        float v01 = fmaxf(c[f][1] + bb1, 0.f);
        float v10 = fmaxf(c[f][2] + bb0, 0.f);
        float v11 = fmaxf(c[f][3] + bb1, 0.f);
        float s0 = 0.f, s1 = 0.f, q0 = 0.f, q1 = 0.f;
        if (ok0) {
            *(float2*)&g_h[(size_t)node0 * D + cl] = make_float2(v00, v01);
            s0 += v00; s1 += v01; q0 += v00 * v00; q1 += v01 * v01;
        }
        if (ok1) {
            *(float2*)&g_h[(size_t)node1 * D + cl] = make_float2(v10, v11);
            s0 += v10; s1 += v11; q0 += v10 * v10; q1 += v11 * v11;
        }
        atomicAdd(&red[cl], s0);
        atomicAdd(&red[cl + 1], s1);
        atomicAdd(&red[D + cl], q0);
        atomicAdd(&red[D + cl + 1], q1);
    }
    __syncthreads();
    if (tid < 2 * D) atomicAdd(&g_stats[tid], (double)red[tid]);
#undef DO_GEMM
#undef LDH
}

// ---------------------------------------------------------------------------
// finalize BN stats (and reset accumulators for next layer)
// ---------------------------------------------------------------------------
__global__ void finalize_kernel() {
    int f = threadIdx.x;
    double s = g_stats[f];
    double q = g_stats[D + f];
    double mu = s / (double)NN;
    double var = q / (double)NN - mu * mu;
    g_mu[f] = (float)mu;
    g_rs[f] = (float)(1.0 / sqrt(var + (double)BN_EPS));
    g_stats[f] = 0.0;
    g_stats[D + f] = 0.0;
}

// ---------------------------------------------------------------------------
// normalize + write xs + next-layer x + pooled segment-sum (batch sorted)
// ---------------------------------------------------------------------------
__global__ void norm_kernel(const float* __restrict__ gamma,
                            const float* __restrict__ beta,
                            const int* __restrict__ batch,
                            float* __restrict__ out_pool,
                            float* __restrict__ out_xs, int layer) {
    int tid = threadIdx.x;
    int f = tid & 63;
    int sub = tid >> 6;   // 0..3
    int base = blockIdx.x * 128;
    float gm = gamma[f], bt = beta[f], mu = g_mu[f], rs = g_rs[f];
    int gcur = -1;
    float acc = 0.f;
    for (int j = 0; j < 32; j++) {
        int n = base + sub + j * 4;
        if (n >= NN) break;
        float h = g_h[(size_t)n * D + f];
        float y = gm * (h - mu) * rs + bt;
        if (out_xs)
            out_xs[(size_t)n * (NL * D) + layer * D + f] = y;
        g_x[(size_t)n * D + f] = y;
        if (out_pool) {
            int g = batch[n];
            if (g != gcur) {
                if (gcur >= 0 && gcur < NG)
                    atomicAdd(&out_pool[(size_t)gcur * (NL * D) + layer * D + f], acc);
                gcur = g;
                acc = 0.f;
            }
            acc += y;
        }
    }
    if (out_pool && gcur >= 0 && gcur < NG)
        atomicAdd(&out_pool[(size_t)gcur * (NL * D) + layer * D + f], acc);
}

// ---------------------------------------------------------------------------
extern "C" void kernel_launch(void* const* d_in, const int* in_sizes, int n_in,
                              void* d_out, int out_size) {
    const float *x = 0, *ew = 0, *W1 = 0, *b1 = 0, *W2 = 0, *b2 = 0,
                *gamma = 0, *beta = 0;
    const int *ei = 0, *batch = 0;
    int n12288 = 0, n192 = 0;
    for (int i = 0; i < n_in; i++) {
        int s = in_sizes[i];
        const void* p = d_in[i];
        if (s == NN * D) x = (const float*)p;
        else if (s == 2 * NE) ei = (const int*)p;
        else if (s == NE) ew = (const float*)p;
        else if (s == NN) batch = (const int*)p;
        else if (s == NL * D * D) {
            if (n12288 == 0) W1 = (const float*)p; else W2 = (const float*)p;
            n12288++;
        } else if (s == NL * D) {
            if (n192 == 0) b1 = (const float*)p;
            else if (n192 == 1) b2 = (const float*)p;
            else if (n192 == 2) gamma = (const float*)p;
            else beta = (const float*)p;
            n192++;
        }
    }

    float* out = (float*)d_out;
    float* out_pool = 0;
    float* out_xs = 0;
    const int POOL_SZ = NG * NL * D;     // 98304
    const int XS_SZ = NN * NL * D;       // 19200000
    if (out_size >= POOL_SZ + XS_SZ) { out_pool = out; out_xs = out + POOL_SZ; }
    else if (out_size >= XS_SZ) { out_xs = out; }
    else { out_pool = out; }

    init_kernel<<<256, 256>>>(out_pool);

    // CSR build (once per call, amortized over 3 layers)
    deg_kernel<<<(NE + 255) / 256, 256>>>(ei);
    scanA_kernel<<<NSCAN, SCAN_BLK>>>();
    scanB_kernel<<<1, 128>>>();
    scanC_kernel<<<(NN + 255) / 256, 256>>>();
    fill_kernel<<<(NE + 255) / 256, 256>>>(ei, ew);

    int agg_blocks = (NN * 32 + 255) / 256;          // 12500
    int mlp_blocks = (NN + 63) / 64;                 // 1563
    int norm_blocks = (NN + 127) / 128;              // 782

    for (int i = 0; i < NL; i++) {
        int use_gx = (i > 0) ? 1 : 0;
        agg_kernel<<<agg_blocks, 256>>>(x, use_gx);
        mlp_kernel<<<mlp_blocks, 256>>>(W1 + i * D * D, b1 + i * D,
                                        W2 + i * D * D, b2 + i * D);
        finalize_kernel<<<1, D>>>();
        norm_kernel<<<norm_blocks, 256>>>(gamma + i * D, beta + i * D,
                                          batch, out_pool, out_xs, i);
    }
}